// round 1
// baseline (speedup 1.0000x reference)
#include <cuda_runtime.h>
#include <cstdint>

// ---------------------------------------------------------------------------
// SelfAttention: out = softmax( (xWq+bq)(xWk+bk)^T / sqrt(512) ) (xWv+bv)
// B=4, S=2048, DIN=1024, DQK=DV=512. fp32 I/O, tf32 tensor-core GEMMs.
// ---------------------------------------------------------------------------

constexpr int B_   = 4;
constexpr int S_   = 2048;
constexpr int DIN  = 1024;
constexpr int DQK  = 512;
constexpr int DV   = 512;
constexpr int MTOT = B_ * S_;   // 8192

// Scratch (allocation-free rule: __device__ globals)
__device__ float g_Q[MTOT * DQK];
__device__ float g_K[MTOT * DQK];
__device__ float g_V[MTOT * DV];
__device__ float g_S[(size_t)B_ * S_ * S_];

__device__ __forceinline__ uint32_t f2tf32(float f) {
    uint32_t u;
    asm("cvt.rna.tf32.f32 %0, %1;" : "=r"(u) : "f"(f));
    return u;
}

__device__ __forceinline__ void mma_tf32(float c[4], const uint32_t a[4], const uint32_t b[2]) {
    asm volatile(
        "mma.sync.aligned.m16n8k8.row.col.f32.tf32.tf32.f32 "
        "{%0,%1,%2,%3}, {%4,%5,%6,%7}, {%8,%9}, {%0,%1,%2,%3};"
        : "+f"(c[0]), "+f"(c[1]), "+f"(c[2]), "+f"(c[3])
        : "r"(a[0]), "r"(a[1]), "r"(a[2]), "r"(a[3]),
          "r"(b[0]), "r"(b[1]));
}

// ---------------------------------------------------------------------------
// Tiled tf32 GEMM:  C[M,N] = scale * (A[M,K] @ B) + bias
//   BT=false: B given as [K,N] row-major (weights, V)
//   BT=true : B given as [N,K] row-major (K matrix; computes A @ B^T)
// Block tile 128x128x32, 256 threads (8 warps: 4 along M x 2 along N),
// warp tile 32x64 = 2x8 m16n8k8 mmas.
// ---------------------------------------------------------------------------
constexpr int BM = 128, BN = 128, BK = 32;

template <bool BT, bool BIAS>
__global__ __launch_bounds__(256)
void gemm_tf32(const float* __restrict__ A, const float* __restrict__ Bm,
               const float* __restrict__ bias, float scale, float* __restrict__ C,
               int M, int N, int K, long sA, long sB, long sC)
{
    A  += (long)blockIdx.z * sA;
    Bm += (long)blockIdx.z * sB;
    C  += (long)blockIdx.z * sC;

    const int m0   = blockIdx.y * BM;
    const int n0   = blockIdx.x * BN;
    const int tid  = threadIdx.x;
    const int lane = tid & 31;
    const int warp = tid >> 5;
    const int wm   = warp & 3;   // 0..3 -> 32-row slabs
    const int wn   = warp >> 2;  // 0..1 -> 64-col slabs

    __shared__ uint32_t As[BM][BK + 1];                 // [m][k], pad 1
    constexpr int BR = BT ? BN : BK;
    constexpr int BC = BT ? (BK + 4) : (BN + 4);        // pads keep float4 alignment
    __shared__ uint32_t Bs[BR][BC];

    float acc[2][8][4];
#pragma unroll
    for (int i = 0; i < 2; i++)
#pragma unroll
        for (int j = 0; j < 8; j++)
#pragma unroll
            for (int r = 0; r < 4; r++) acc[i][j][r] = 0.0f;

    for (int k0 = 0; k0 < K; k0 += BK) {
        // ---- load A tile (128 x 32), convert to tf32 ----
        {
            const int r  = tid >> 3;   // 0..31
            const int cq = tid & 7;    // float4 col 0..7
#pragma unroll
            for (int p = 0; p < 4; p++) {
                const int row = r + p * 32;
                float4 v = *reinterpret_cast<const float4*>(
                    A + (size_t)(m0 + row) * K + k0 + cq * 4);
                uint32_t* d = &As[row][cq * 4];
                d[0] = f2tf32(v.x); d[1] = f2tf32(v.y);
                d[2] = f2tf32(v.z); d[3] = f2tf32(v.w);
            }
        }
        // ---- load B tile ----
        if (BT) {
            // B is [N,K] row-major: tile 128n x 32k, store Bs[n][k]
            const int r  = tid >> 3;   // n row 0..31
            const int cq = tid & 7;    // float4 k idx 0..7
#pragma unroll
            for (int p = 0; p < 4; p++) {
                const int nrow = r + p * 32;
                float4 v = *reinterpret_cast<const float4*>(
                    Bm + (size_t)(n0 + nrow) * K + k0 + cq * 4);
                uint4 w = make_uint4(f2tf32(v.x), f2tf32(v.y), f2tf32(v.z), f2tf32(v.w));
                *reinterpret_cast<uint4*>(&Bs[nrow][cq * 4]) = w;
            }
        } else {
            // B is [K,N] row-major: tile 32k x 128n, store Bs[k][n]
            const int r  = tid >> 5;   // k row 0..7
            const int cq = tid & 31;   // float4 n idx 0..31
#pragma unroll
            for (int p = 0; p < 4; p++) {
                const int krow = r + p * 8;
                float4 v = *reinterpret_cast<const float4*>(
                    Bm + (size_t)(k0 + krow) * N + n0 + cq * 4);
                uint4 w = make_uint4(f2tf32(v.x), f2tf32(v.y), f2tf32(v.z), f2tf32(v.w));
                *reinterpret_cast<uint4*>(&Bs[krow][cq * 4]) = w;
            }
        }
        __syncthreads();

#pragma unroll
        for (int ks = 0; ks < BK / 8; ks++) {
            const int kb = ks * 8;
            uint32_t af[2][4];
#pragma unroll
            for (int mi = 0; mi < 2; mi++) {
                const int m  = wm * 32 + mi * 16 + (lane >> 2);
                const int kk = kb + (lane & 3);
                af[mi][0] = As[m][kk];
                af[mi][1] = As[m + 8][kk];
                af[mi][2] = As[m][kk + 4];
                af[mi][3] = As[m + 8][kk + 4];
            }
            uint32_t bf[8][2];
#pragma unroll
            for (int ni = 0; ni < 8; ni++) {
                const int n  = wn * 64 + ni * 8 + (lane >> 2);
                const int kk = kb + (lane & 3);
                if (BT) { bf[ni][0] = Bs[n][kk];  bf[ni][1] = Bs[n][kk + 4]; }
                else    { bf[ni][0] = Bs[kk][n];  bf[ni][1] = Bs[kk + 4][n]; }
            }
#pragma unroll
            for (int mi = 0; mi < 2; mi++)
#pragma unroll
                for (int ni = 0; ni < 8; ni++)
                    mma_tf32(acc[mi][ni], af[mi], bf[ni]);
        }
        __syncthreads();
    }

    // ---- epilogue: scale (+bias) and store ----
#pragma unroll
    for (int mi = 0; mi < 2; mi++) {
#pragma unroll
        for (int ni = 0; ni < 8; ni++) {
            const int row = m0 + wm * 32 + mi * 16 + (lane >> 2);
            const int col = n0 + wn * 64 + ni * 8 + 2 * (lane & 3);
            float b0 = 0.0f, b1 = 0.0f;
            if (BIAS) { b0 = bias[col]; b1 = bias[col + 1]; }
            float* c0 = C + (size_t)row * N + col;
            c0[0] = acc[mi][ni][0] * scale + b0;
            c0[1] = acc[mi][ni][1] * scale + b1;
            float* c1 = C + (size_t)(row + 8) * N + col;
            c1[0] = acc[mi][ni][2] * scale + b0;
            c1[1] = acc[mi][ni][3] * scale + b1;
        }
    }
}

// ---------------------------------------------------------------------------
// Row softmax over 2048 cols. One block per row, values register-resident:
// exactly one read + one write of the 64MB score buffer.
// ---------------------------------------------------------------------------
__global__ __launch_bounds__(256)
void softmax2048(float* __restrict__ Sm)
{
    const int tid = threadIdx.x;
    float* row = Sm + (size_t)blockIdx.x * 2048;

    float v[8];
    float mx = -3.4e38f;
#pragma unroll
    for (int i = 0; i < 8; i++) { v[i] = row[tid + 256 * i]; mx = fmaxf(mx, v[i]); }

    __shared__ float sh[8];
    const int wid = tid >> 5, lane = tid & 31;

#pragma unroll
    for (int o = 16; o > 0; o >>= 1) mx = fmaxf(mx, __shfl_xor_sync(0xffffffffu, mx, o));
    if (lane == 0) sh[wid] = mx;
    __syncthreads();
    if (tid == 0) {
        float m2 = sh[0];
#pragma unroll
        for (int i = 1; i < 8; i++) m2 = fmaxf(m2, sh[i]);
        sh[0] = m2;
    }
    __syncthreads();
    mx = sh[0];
    __syncthreads();

    float s = 0.0f;
#pragma unroll
    for (int i = 0; i < 8; i++) { v[i] = __expf(v[i] - mx); s += v[i]; }
#pragma unroll
    for (int o = 16; o > 0; o >>= 1) s += __shfl_xor_sync(0xffffffffu, s, o);
    if (lane == 0) sh[wid] = s;
    __syncthreads();
    if (tid == 0) {
        float t = 0.0f;
#pragma unroll
        for (int i = 0; i < 8; i++) t += sh[i];
        sh[0] = t;
    }
    __syncthreads();
    const float inv = 1.0f / sh[0];

#pragma unroll
    for (int i = 0; i < 8; i++) row[tid + 256 * i] = v[i] * inv;
}

// ---------------------------------------------------------------------------
// Launch
// ---------------------------------------------------------------------------
extern "C" void kernel_launch(void* const* d_in, const int* in_sizes, int n_in,
                              void* d_out, int out_size)
{
    const float* x  = (const float*)d_in[0];
    const float* Wq = (const float*)d_in[1];
    const float* bq = (const float*)d_in[2];
    const float* Wk = (const float*)d_in[3];
    const float* bk = (const float*)d_in[4];
    const float* Wv = (const float*)d_in[5];
    const float* bv = (const float*)d_in[6];
    float* out = (float*)d_out;

    float *Q, *K, *V, *Sc;
    cudaGetSymbolAddress((void**)&Q,  g_Q);
    cudaGetSymbolAddress((void**)&K,  g_K);
    cudaGetSymbolAddress((void**)&V,  g_V);
    cudaGetSymbolAddress((void**)&Sc, g_S);

    const dim3 blk(256);

    // 1) Projections: Q/K/V = x @ W + b   (8192 x 512 x 1024)
    const dim3 gproj(DQK / BN, MTOT / BM, 1);
    gemm_tf32<false, true><<<gproj, blk>>>(x, Wq, bq, 1.0f, Q, MTOT, DQK, DIN, 0, 0, 0);
    gemm_tf32<false, true><<<gproj, blk>>>(x, Wk, bk, 1.0f, K, MTOT, DQK, DIN, 0, 0, 0);
    gemm_tf32<false, true><<<gproj, blk>>>(x, Wv, bv, 1.0f, V, MTOT, DV,  DIN, 0, 0, 0);

    // 2) Scores: S = (Q @ K^T) / sqrt(512)   per batch 2048 x 2048 x 512
    const float scale = 0.044194173824159216f;  // 1/sqrt(512)
    gemm_tf32<true, false><<<dim3(S_ / BN, S_ / BM, B_), blk>>>(
        Q, K, nullptr, scale, Sc, S_, S_, DQK,
        (long)S_ * DQK, (long)S_ * DQK, (long)S_ * S_);

    // 3) Softmax over rows
    softmax2048<<<B_ * S_, blk>>>(Sc);

    // 4) Out = P @ V   per batch 2048 x 512 x 2048
    gemm_tf32<false, false><<<dim3(DV / BN, S_ / BM, B_), blk>>>(
        Sc, V, nullptr, 1.0f, out, S_, DV, S_,
        (long)S_ * S_, (long)S_ * DV, (long)S_ * DV);
}

// round 3
// speedup vs baseline: 1.5503x; 1.5503x over previous
#include <cuda_runtime.h>
#include <cstdint>

// ---------------------------------------------------------------------------
// SelfAttention, tf32 mma.sync + ldmatrix-fed fragments (sm_103 PTX-safe:
// tcgen05 is rejected by ptxas on compute_103 target, so legacy tensor path).
// B=4, S=2048, DIN=1024, DQK=DV=512, fp32 I/O.
// ---------------------------------------------------------------------------

constexpr int B_   = 4;
constexpr int S_   = 2048;
constexpr int DIN  = 1024;
constexpr int DQK  = 512;
constexpr int DV   = 512;
constexpr int MTOT = B_ * S_;   // 8192

// Scratch (__device__ globals; allocation-free rule)
__device__ float g_Q [MTOT * DQK];
__device__ float g_K [MTOT * DQK];
__device__ float g_Vt[MTOT * DV];            // per batch: [DV][S]
__device__ float g_S [(size_t)B_ * S_ * S_];
__device__ float g_Wt[3][DQK * DIN];         // W^T: [N=512][K=1024]

__device__ __forceinline__ uint32_t smem_u32(const void* p) {
    uint32_t a;
    asm("{ .reg .u64 t; cvta.to.shared.u64 t, %1; cvt.u32.u64 %0, t; }" : "=r"(a) : "l"(p));
    return a;
}
__device__ __forceinline__ uint32_t f2tf32(float f) {
    uint32_t u;
    asm("cvt.rna.tf32.f32 %0, %1;" : "=r"(u) : "f"(f));
    return u;
}
__device__ __forceinline__ uint32_t swz128(uint32_t off) {
    return off ^ ((off >> 3) & 0x70);
}

#define LDSM_X4(r0, r1, r2, r3, a)                                          \
    asm volatile("ldmatrix.sync.aligned.m8n8.x4.shared.b16 {%0,%1,%2,%3}, [%4];" \
                 : "=r"(r0), "=r"(r1), "=r"(r2), "=r"(r3) : "r"(a))

__device__ __forceinline__ void mma_tf32(float c[4], const uint32_t a[4],
                                         uint32_t b0, uint32_t b1) {
    asm volatile(
        "mma.sync.aligned.m16n8k8.row.col.f32.tf32.tf32.f32 "
        "{%0,%1,%2,%3}, {%4,%5,%6,%7}, {%8,%9}, {%0,%1,%2,%3};"
        : "+f"(c[0]), "+f"(c[1]), "+f"(c[2]), "+f"(c[3])
        : "r"(a[0]), "r"(a[1]), "r"(a[2]), "r"(a[3]), "r"(b0), "r"(b1));
}

// ---------------------------------------------------------------------------
// GEMM: C[M,N] = scale * (A[M,K] @ B[N,K]^T) (+ bias[n])
// CTA tile 128x128x32, 256 threads, 8 warps of 32(m)x64(n).
// SMEM tiles 128 rows x 128B (32 tf32), SW128-swizzled, double buffered.
// Fragments fed by ldmatrix.x4 (b16 view of tf32).
// ---------------------------------------------------------------------------
constexpr int BM = 128, BN = 128, BKC = 32;
constexpr int TILE_B  = 128 * 128;          // 16 KB
constexpr int SMEM_SZ = 4 * TILE_B;         // A0,B0,A1,B1 = 64 KB

__device__ __forceinline__ void ldg_chunk(const float* __restrict__ src, int ld,
                                          int k0, int tid, uint4 st[4]) {
    const int q = tid & 7;
#pragma unroll
    for (int p = 0; p < 4; p++) {
        const int row = (tid >> 3) + p * 32;
        float4 v = *reinterpret_cast<const float4*>(src + (size_t)row * ld + k0 + q * 4);
        st[p] = make_uint4(f2tf32(v.x), f2tf32(v.y), f2tf32(v.z), f2tf32(v.w));
    }
}
__device__ __forceinline__ void sts_chunk(char* dst, int tid, const uint4 st[4]) {
    const int q = tid & 7;
#pragma unroll
    for (int p = 0; p < 4; p++) {
        const int row = (tid >> 3) + p * 32;
        *reinterpret_cast<uint4*>(dst + swz128((uint32_t)(row * 128 + q * 16))) = st[p];
    }
}

template <bool BIAS, bool CTRANS>
__global__ __launch_bounds__(256)
void gemm_ldsm(const float* __restrict__ A, const float* __restrict__ Bm,
               const float* __restrict__ bias, float scale, float* __restrict__ C,
               int lda, int ldb, int ldc, int K,
               long sA, long sB, long sC)
{
    extern __shared__ __align__(1024) char smem[];

    A  += (long)blockIdx.z * sA;
    Bm += (long)blockIdx.z * sB;
    C  += (long)blockIdx.z * sC;

    const int m0   = blockIdx.y * BM;
    const int n0   = blockIdx.x * BN;
    const int tid  = threadIdx.x;
    const int lane = tid & 31;
    const int wid  = tid >> 5;
    const int wm   = wid & 3;    // 4 x 32-row slabs
    const int wn   = wid >> 2;   // 2 x 64-col slabs

    // per-lane ldmatrix decomposition: 4 address-groups of 8 lanes
    const int lr  = lane & 7;
    const int b8  = lane >> 3;          // 0..3
    const int aro = (b8 & 1) * 8 + lr;  // A: row offset within m16 tile
    const int ach = b8 >> 1;            // A: extra k-chunk (0/1)
    const int bro = (b8 >> 1) * 8 + lr; // B: n offset within ni-pair
    const int bch = b8 & 1;             // B: extra k-chunk (0/1)

    const float* Ab = A  + (size_t)m0 * lda;
    const float* Bb = Bm + (size_t)n0 * ldb;
    const int NC = K / BKC;

    float acc[2][8][4];
#pragma unroll
    for (int i = 0; i < 2; i++)
#pragma unroll
        for (int j = 0; j < 8; j++)
#pragma unroll
            for (int r = 0; r < 4; r++) acc[i][j][r] = 0.0f;

    // prologue: chunk 0 -> buffer 0
    {
        uint4 ra[4], rb[4];
        ldg_chunk(Ab, lda, 0, tid, ra);
        ldg_chunk(Bb, ldb, 0, tid, rb);
        sts_chunk(smem, tid, ra);
        sts_chunk(smem + TILE_B, tid, rb);
    }
    __syncthreads();

    for (int c = 0; c < NC; c++) {
        uint4 ra[4], rb[4];
        const bool more = (c + 1 < NC);
        if (more) {   // issue global loads early; MMAs below hide latency
            ldg_chunk(Ab, lda, (c + 1) * BKC, tid, ra);
            ldg_chunk(Bb, ldb, (c + 1) * BKC, tid, rb);
        }

        const uint32_t baseA = smem_u32(smem + (c & 1) * 2 * TILE_B);
        const uint32_t baseB = baseA + TILE_B;

#pragma unroll
        for (int ks = 0; ks < 4; ks++) {
            uint32_t a[2][4];
#pragma unroll
            for (int mi = 0; mi < 2; mi++) {
                const uint32_t off =
                    (uint32_t)((wm * 32 + mi * 16 + aro) * 128 + (ks * 2 + ach) * 16);
                LDSM_X4(a[mi][0], a[mi][1], a[mi][2], a[mi][3], baseA + swz128(off));
            }
            uint32_t bq[4][4];
#pragma unroll
            for (int p = 0; p < 4; p++) {
                const uint32_t off =
                    (uint32_t)((wn * 64 + p * 16 + bro) * 128 + (ks * 2 + bch) * 16);
                LDSM_X4(bq[p][0], bq[p][1], bq[p][2], bq[p][3], baseB + swz128(off));
            }
#pragma unroll
            for (int mi = 0; mi < 2; mi++)
#pragma unroll
                for (int ni = 0; ni < 8; ni++)
                    mma_tf32(acc[mi][ni], a[mi],
                             bq[ni >> 1][(ni & 1) * 2], bq[ni >> 1][(ni & 1) * 2 + 1]);
        }

        if (more) {
            char* nb = smem + ((c + 1) & 1) * 2 * TILE_B;
            sts_chunk(nb, tid, ra);
            sts_chunk(nb + TILE_B, tid, rb);
        }
        __syncthreads();
    }

    // epilogue
#pragma unroll
    for (int mi = 0; mi < 2; mi++) {
#pragma unroll
        for (int ni = 0; ni < 8; ni++) {
            const int row = m0 + wm * 32 + mi * 16 + (lane >> 2);
            const int col = n0 + wn * 64 + ni * 8 + 2 * (lane & 3);
            float b0 = 0.0f, b1 = 0.0f;
            if (BIAS) { b0 = __ldg(bias + col); b1 = __ldg(bias + col + 1); }
            float v00 = acc[mi][ni][0] * scale + b0;
            float v01 = acc[mi][ni][1] * scale + b1;
            float v10 = acc[mi][ni][2] * scale + b0;
            float v11 = acc[mi][ni][3] * scale + b1;
            if (CTRANS) {
                // write V transposed: Vt[b][col][s]
                const int bb0 = row >> 11, s0 = row & 2047;
                const int bb1 = (row + 8) >> 11, s1 = (row + 8) & 2047;
                C[((size_t)(bb0 * DV + col))     * S_ + s0] = v00;
                C[((size_t)(bb0 * DV + col + 1)) * S_ + s0] = v01;
                C[((size_t)(bb1 * DV + col))     * S_ + s1] = v10;
                C[((size_t)(bb1 * DV + col + 1)) * S_ + s1] = v11;
            } else {
                float* c0 = C + (size_t)row * ldc + col;
                c0[0] = v00; c0[1] = v01;
                float* c1 = C + (size_t)(row + 8) * ldc + col;
                c1[0] = v10; c1[1] = v11;
            }
        }
    }
}

// ---------------------------------------------------------------------------
// Weight transpose: out[C][R] = in[R][C]
// ---------------------------------------------------------------------------
__global__ __launch_bounds__(256)
void transpose_k(const float* __restrict__ in, float* __restrict__ out, int R, int C)
{
    __shared__ float t[32][33];
    const int bx = blockIdx.x * 32, by = blockIdx.y * 32;
    const int tx = threadIdx.x, ty = threadIdx.y;
#pragma unroll
    for (int i = 0; i < 4; i++)
        t[ty + 8 * i][tx] = in[(size_t)(by + ty + 8 * i) * C + bx + tx];
    __syncthreads();
#pragma unroll
    for (int i = 0; i < 4; i++)
        out[(size_t)(bx + ty + 8 * i) * R + by + tx] = t[tx][ty + 8 * i];
}

// ---------------------------------------------------------------------------
// Row softmax over 2048 cols (register-resident, 1R+1W)
// ---------------------------------------------------------------------------
__global__ __launch_bounds__(256)
void softmax2048(float* __restrict__ Sm)
{
    const int tid = threadIdx.x;
    float* row = Sm + (size_t)blockIdx.x * 2048;

    float v[8];
    float mx = -3.4e38f;
#pragma unroll
    for (int i = 0; i < 8; i++) { v[i] = row[tid + 256 * i]; mx = fmaxf(mx, v[i]); }

    __shared__ float sh[8];
    const int wid = tid >> 5, lane = tid & 31;
#pragma unroll
    for (int o = 16; o > 0; o >>= 1) mx = fmaxf(mx, __shfl_xor_sync(0xffffffffu, mx, o));
    if (lane == 0) sh[wid] = mx;
    __syncthreads();
    if (tid == 0) {
        float m2 = sh[0];
#pragma unroll
        for (int i = 1; i < 8; i++) m2 = fmaxf(m2, sh[i]);
        sh[0] = m2;
    }
    __syncthreads();
    mx = sh[0];
    __syncthreads();

    float s = 0.0f;
#pragma unroll
    for (int i = 0; i < 8; i++) { v[i] = __expf(v[i] - mx); s += v[i]; }
#pragma unroll
    for (int o = 16; o > 0; o >>= 1) s += __shfl_xor_sync(0xffffffffu, s, o);
    if (lane == 0) sh[wid] = s;
    __syncthreads();
    if (tid == 0) {
        float t = 0.0f;
#pragma unroll
        for (int i = 0; i < 8; i++) t += sh[i];
        sh[0] = t;
    }
    __syncthreads();
    const float inv = 1.0f / sh[0];
#pragma unroll
    for (int i = 0; i < 8; i++) row[tid + 256 * i] = v[i] * inv;
}

// ---------------------------------------------------------------------------
// Launch
// ---------------------------------------------------------------------------
extern "C" void kernel_launch(void* const* d_in, const int* in_sizes, int n_in,
                              void* d_out, int out_size)
{
    const float* x  = (const float*)d_in[0];
    const float* Wq = (const float*)d_in[1];
    const float* bq = (const float*)d_in[2];
    const float* Wk = (const float*)d_in[3];
    const float* bk = (const float*)d_in[4];
    const float* Wv = (const float*)d_in[5];
    const float* bv = (const float*)d_in[6];
    float* out = (float*)d_out;

    float *Q, *K, *Vt, *Sc, *Wt;
    cudaGetSymbolAddress((void**)&Q,  g_Q);
    cudaGetSymbolAddress((void**)&K,  g_K);
    cudaGetSymbolAddress((void**)&Vt, g_Vt);
    cudaGetSymbolAddress((void**)&Sc, g_S);
    cudaGetSymbolAddress((void**)&Wt, g_Wt);
    float* Wtq = Wt;
    float* Wtk = Wt + (size_t)DQK * DIN;
    float* Wtv = Wt + 2 * (size_t)DQK * DIN;

    cudaFuncSetAttribute(gemm_ldsm<true,  false>, cudaFuncAttributeMaxDynamicSharedMemorySize, SMEM_SZ);
    cudaFuncSetAttribute(gemm_ldsm<true,  true >, cudaFuncAttributeMaxDynamicSharedMemorySize, SMEM_SZ);
    cudaFuncSetAttribute(gemm_ldsm<false, false>, cudaFuncAttributeMaxDynamicSharedMemorySize, SMEM_SZ);

    // 0) Transpose weights to [N][K]
    const dim3 tb(32, 8), tg(DQK / 32, DIN / 32);
    transpose_k<<<tg, tb>>>(Wq, Wtq, DIN, DQK);
    transpose_k<<<tg, tb>>>(Wk, Wtk, DIN, DQK);
    transpose_k<<<tg, tb>>>(Wv, Wtv, DIN, DQK);

    const dim3 blk(256);

    // 1) Projections (M=8192, N=512, K=1024); V written transposed
    const dim3 gproj(DQK / BN, MTOT / BM, 1);
    gemm_ldsm<true, false><<<gproj, blk, SMEM_SZ>>>(x, Wtq, bq, 1.0f, Q,  DIN, DIN, DQK, DIN, 0, 0, 0);
    gemm_ldsm<true, false><<<gproj, blk, SMEM_SZ>>>(x, Wtk, bk, 1.0f, K,  DIN, DIN, DQK, DIN, 0, 0, 0);
    gemm_ldsm<true, true ><<<gproj, blk, SMEM_SZ>>>(x, Wtv, bv, 1.0f, Vt, DIN, DIN, 0,   DIN, 0, 0, 0);

    // 2) Scores: S = (Q @ K^T) / sqrt(512)  per batch 2048x2048x512
    const float scale = 0.044194173824159216f;
    gemm_ldsm<false, false><<<dim3(S_ / BN, S_ / BM, B_), blk, SMEM_SZ>>>(
        Q, K, nullptr, scale, Sc, DQK, DQK, S_, DQK,
        (long)S_ * DQK, (long)S_ * DQK, (long)S_ * S_);

    // 3) Softmax
    softmax2048<<<B_ * S_, blk>>>(Sc);

    // 4) Out = P @ Vt^T  per batch 2048x512x2048
    gemm_ldsm<false, false><<<dim3(DV / BN, S_ / BM, B_), blk, SMEM_SZ>>>(
        Sc, Vt, nullptr, 1.0f, out, S_, S_, DV, S_,
        (long)S_ * S_, (long)DV * S_, (long)S_ * DV);
}

// round 4
// speedup vs baseline: 2.8929x; 1.8660x over previous
#include <cuda_runtime.h>
#include <cstdint>

// ---------------------------------------------------------------------------
// SelfAttention, tf32 mma.sync + ldmatrix + cp.async 3-stage pipeline.
// All GEMM operands pre-rounded to tf32 by their producers, so the GEMM
// hot loop has zero cvt work and zero register staging.
// B=4, S=2048, DIN=1024, DQK=DV=512, fp32 I/O.
// ---------------------------------------------------------------------------

constexpr int B_   = 4;
constexpr int S_   = 2048;
constexpr int DIN  = 1024;
constexpr int DQK  = 512;
constexpr int DV   = 512;
constexpr int MTOT = B_ * S_;    // 8192
constexpr int NPROJ = 3 * DQK;   // 1536 (Q|K|V concat)

// Scratch (__device__ globals; allocation-free rule)
__device__ float g_Xr[MTOT * DIN];           // x rounded to tf32
__device__ float g_Q [MTOT * DQK];
__device__ float g_K [MTOT * DQK];
__device__ float g_Vt[MTOT * DV];            // per batch: [DV][S]
__device__ float g_S [(size_t)B_ * S_ * S_];
__device__ float g_Wt[NPROJ * DIN];          // W^T concat: [1536][1024]
__device__ float g_bc[NPROJ];                // bias concat

__device__ __forceinline__ uint32_t smem_u32(const void* p) {
    uint32_t a;
    asm("{ .reg .u64 t; cvta.to.shared.u64 t, %1; cvt.u32.u64 %0, t; }" : "=r"(a) : "l"(p));
    return a;
}
__device__ __forceinline__ uint32_t f2tf32(float f) {
    uint32_t u;
    asm("cvt.rna.tf32.f32 %0, %1;" : "=r"(u) : "f"(f));
    return u;
}
__device__ __forceinline__ float roundtf(float f) { return __uint_as_float(f2tf32(f)); }
__device__ __forceinline__ uint32_t swz128(uint32_t off) {
    return off ^ ((off >> 3) & 0x70);
}

#define LDSM_X4(r0, r1, r2, r3, a)                                          \
    asm volatile("ldmatrix.sync.aligned.m8n8.x4.shared.b16 {%0,%1,%2,%3}, [%4];" \
                 : "=r"(r0), "=r"(r1), "=r"(r2), "=r"(r3) : "r"(a))

__device__ __forceinline__ void mma_tf32(float c[4], const uint32_t a[4],
                                         uint32_t b0, uint32_t b1) {
    asm volatile(
        "mma.sync.aligned.m16n8k8.row.col.f32.tf32.tf32.f32 "
        "{%0,%1,%2,%3}, {%4,%5,%6,%7}, {%8,%9}, {%0,%1,%2,%3};"
        : "+f"(c[0]), "+f"(c[1]), "+f"(c[2]), "+f"(c[3])
        : "r"(a[0]), "r"(a[1]), "r"(a[2]), "r"(a[3]), "r"(b0), "r"(b1));
}

__device__ __forceinline__ void cp16(uint32_t s, const void* g) {
    asm volatile("cp.async.cg.shared.global [%0], [%1], 16;" :: "r"(s), "l"(g));
}
#define CP_COMMIT() asm volatile("cp.async.commit_group;" ::: "memory")
#define CP_WAIT1()  asm volatile("cp.async.wait_group 1;"  ::: "memory")

// ---------------------------------------------------------------------------
// GEMM: C = scale * (A[M,K] @ B[N,K]^T) (+ bias); CTA 128x128x32; 256 thr;
// 8 warps of 32(m)x64(n); SW128-swizzled SMEM; cp.async 3-stage pipeline.
// PROJ=true: fused QKV projection (N=1536): bias add, tf32-rounded stores,
//            cols [0,512)->C0(Q), [512,1024)->C1(K), [1024,1536)->C2(Vt,
//            written transposed per batch).
// ---------------------------------------------------------------------------
constexpr int BM = 128, BN = 128, BKC = 32, STAGES = 3;
constexpr int TILE_B  = 128 * 128;            // 16 KB per matrix tile
constexpr int STAGE_B = 2 * TILE_B;           // 32 KB
constexpr int SMEM_SZ = STAGES * STAGE_B;     // 96 KB

__device__ __forceinline__ void copy_tile(uint32_t sdst, const float* __restrict__ src,
                                          int ld, int k0, int tid) {
    const int q = tid & 7, r0 = tid >> 3;
#pragma unroll
    for (int p = 0; p < 4; p++) {
        const int row = r0 + p * 32;
        cp16(sdst + swz128((uint32_t)(row * 128 + q * 16)),
             src + (size_t)row * ld + k0 + q * 4);
    }
}

template <bool PROJ>
__global__ __launch_bounds__(256, 2)
void gemm_ca(const float* __restrict__ A, const float* __restrict__ Bm,
             const float* __restrict__ bias, float scale,
             float* __restrict__ C0, float* __restrict__ C1, float* __restrict__ C2,
             int lda, int ldb, int ldc, int K,
             long sA, long sB, long sC)
{
    extern __shared__ __align__(1024) char smem[];
    const uint32_t sb = smem_u32(smem);

    A  += (long)blockIdx.z * sA;
    Bm += (long)blockIdx.z * sB;
    float* C = C0 + (long)blockIdx.z * sC;

    const int m0   = blockIdx.y * BM;
    const int n0   = blockIdx.x * BN;
    const int tid  = threadIdx.x;
    const int lane = tid & 31;
    const int wid  = tid >> 5;
    const int wm   = wid & 3;
    const int wn   = wid >> 2;

    const int lr  = lane & 7;
    const int b8  = lane >> 3;
    const int aro = (b8 & 1) * 8 + lr;
    const int ach = b8 >> 1;
    const int bro = (b8 >> 1) * 8 + lr;
    const int bch = b8 & 1;

    const float* Ab = A  + (size_t)m0 * lda;
    const float* Bb = Bm + (size_t)n0 * ldb;
    const int NC = K / BKC;

    float acc[2][8][4];
#pragma unroll
    for (int i = 0; i < 2; i++)
#pragma unroll
        for (int j = 0; j < 8; j++)
#pragma unroll
            for (int r = 0; r < 4; r++) acc[i][j][r] = 0.0f;

    // prologue: stages 0,1 in flight
    copy_tile(sb,                    Ab, lda, 0, tid);
    copy_tile(sb + TILE_B,           Bb, ldb, 0, tid);
    CP_COMMIT();
    copy_tile(sb + STAGE_B,          Ab, lda, BKC, tid);
    copy_tile(sb + STAGE_B + TILE_B, Bb, ldb, BKC, tid);
    CP_COMMIT();

    int bufc = 0, bufn = 2;
    for (int c = 0; c < NC; c++) {
        CP_WAIT1();
        __syncthreads();

        if (c + 2 < NC) {
            const uint32_t d = sb + bufn * STAGE_B;
            copy_tile(d,          Ab, lda, (c + 2) * BKC, tid);
            copy_tile(d + TILE_B, Bb, ldb, (c + 2) * BKC, tid);
        }
        CP_COMMIT();  // always commit: keeps wait_group accounting uniform

        const uint32_t baseA = sb + bufc * STAGE_B;
        const uint32_t baseB = baseA + TILE_B;
#pragma unroll
        for (int ks = 0; ks < 4; ks++) {
            uint32_t a[2][4];
#pragma unroll
            for (int mi = 0; mi < 2; mi++) {
                const uint32_t off =
                    (uint32_t)((wm * 32 + mi * 16 + aro) * 128 + (ks * 2 + ach) * 16);
                LDSM_X4(a[mi][0], a[mi][1], a[mi][2], a[mi][3], baseA + swz128(off));
            }
            uint32_t bq[4][4];
#pragma unroll
            for (int p = 0; p < 4; p++) {
                const uint32_t off =
                    (uint32_t)((wn * 64 + p * 16 + bro) * 128 + (ks * 2 + bch) * 16);
                LDSM_X4(bq[p][0], bq[p][1], bq[p][2], bq[p][3], baseB + swz128(off));
            }
#pragma unroll
            for (int mi = 0; mi < 2; mi++)
#pragma unroll
                for (int ni = 0; ni < 8; ni++)
                    mma_tf32(acc[mi][ni], a[mi],
                             bq[ni >> 1][(ni & 1) * 2], bq[ni >> 1][(ni & 1) * 2 + 1]);
        }
        bufc = (bufc == 2) ? 0 : bufc + 1;
        bufn = (bufn == 2) ? 0 : bufn + 1;
    }

    // epilogue
#pragma unroll
    for (int mi = 0; mi < 2; mi++) {
#pragma unroll
        for (int ni = 0; ni < 8; ni++) {
            const int row = m0 + wm * 32 + mi * 16 + (lane >> 2);
            const int col = n0 + wn * 64 + ni * 8 + 2 * (lane & 3);
            if (PROJ) {
                const float b0 = __ldg(bias + col);
                const float b1 = __ldg(bias + col + 1);
                const float v00 = roundtf(acc[mi][ni][0] + b0);
                const float v01 = roundtf(acc[mi][ni][1] + b1);
                const float v10 = roundtf(acc[mi][ni][2] + b0);
                const float v11 = roundtf(acc[mi][ni][3] + b1);
                if (col < 1024) {
                    float* dst = (col < 512) ? C0 : C1;
                    const int cc = col & 511;
                    float* c0 = dst + (size_t)row * DQK + cc;
                    c0[0] = v00; c0[1] = v01;
                    float* c1 = dst + (size_t)(row + 8) * DQK + cc;
                    c1[0] = v10; c1[1] = v11;
                } else {
                    const int vc = col - 1024;
                    const int bb0 = row >> 11, s0 = row & 2047;
                    const int bb1 = (row + 8) >> 11, s1 = (row + 8) & 2047;
                    C2[((size_t)(bb0 * DV + vc))     * S_ + s0] = v00;
                    C2[((size_t)(bb0 * DV + vc + 1)) * S_ + s0] = v01;
                    C2[((size_t)(bb1 * DV + vc))     * S_ + s1] = v10;
                    C2[((size_t)(bb1 * DV + vc + 1)) * S_ + s1] = v11;
                }
            } else {
                float* c0 = C + (size_t)row * ldc + col;
                c0[0] = acc[mi][ni][0] * scale;
                c0[1] = acc[mi][ni][1] * scale;
                float* c1 = C + (size_t)(row + 8) * ldc + col;
                c1[0] = acc[mi][ni][2] * scale;
                c1[1] = acc[mi][ni][3] * scale;
            }
        }
    }
}

// ---------------------------------------------------------------------------
// x -> tf32-rounded copy
// ---------------------------------------------------------------------------
__global__ __launch_bounds__(256)
void round_x(const float* __restrict__ in, float* __restrict__ out, int n4)
{
    const int i = blockIdx.x * blockDim.x + threadIdx.x;
    if (i < n4) {
        float4 v = reinterpret_cast<const float4*>(in)[i];
        v.x = roundtf(v.x); v.y = roundtf(v.y);
        v.z = roundtf(v.z); v.w = roundtf(v.w);
        reinterpret_cast<float4*>(out)[i] = v;
    }
}

// ---------------------------------------------------------------------------
// Weight transpose + tf32 round: out[C][R] = round(in[R][C])
// ---------------------------------------------------------------------------
__global__ __launch_bounds__(256)
void transpose_k(const float* __restrict__ in, float* __restrict__ out, int R, int C)
{
    __shared__ float t[32][33];
    const int bx = blockIdx.x * 32, by = blockIdx.y * 32;
    const int tx = threadIdx.x, ty = threadIdx.y;
#pragma unroll
    for (int i = 0; i < 4; i++)
        t[ty + 8 * i][tx] = in[(size_t)(by + ty + 8 * i) * C + bx + tx];
    __syncthreads();
#pragma unroll
    for (int i = 0; i < 4; i++)
        out[(size_t)(bx + ty + 8 * i) * R + by + tx] = roundtf(t[tx][ty + 8 * i]);
}

__global__ void concat_bias(const float* __restrict__ bq, const float* __restrict__ bk,
                            const float* __restrict__ bv, float* __restrict__ bc)
{
    const int i = blockIdx.x * blockDim.x + threadIdx.x;
    if (i < DQK)            bc[i] = bq[i];
    else if (i < 2 * DQK)   bc[i] = bk[i - DQK];
    else if (i < 3 * DQK)   bc[i] = bv[i - 2 * DQK];
}

// ---------------------------------------------------------------------------
// Row softmax over 2048 cols; stores tf32-rounded probabilities.
// ---------------------------------------------------------------------------
__global__ __launch_bounds__(256)
void softmax2048(float* __restrict__ Sm)
{
    const int tid = threadIdx.x;
    float* row = Sm + (size_t)blockIdx.x * 2048;

    float v[8];
    float mx = -3.4e38f;
#pragma unroll
    for (int i = 0; i < 8; i++) { v[i] = row[tid + 256 * i]; mx = fmaxf(mx, v[i]); }

    __shared__ float sh[8];
    const int wid = tid >> 5, lane = tid & 31;
#pragma unroll
    for (int o = 16; o > 0; o >>= 1) mx = fmaxf(mx, __shfl_xor_sync(0xffffffffu, mx, o));
    if (lane == 0) sh[wid] = mx;
    __syncthreads();
    if (tid == 0) {
        float m2 = sh[0];
#pragma unroll
        for (int i = 1; i < 8; i++) m2 = fmaxf(m2, sh[i]);
        sh[0] = m2;
    }
    __syncthreads();
    mx = sh[0];
    __syncthreads();

    float s = 0.0f;
#pragma unroll
    for (int i = 0; i < 8; i++) { v[i] = __expf(v[i] - mx); s += v[i]; }
#pragma unroll
    for (int o = 16; o > 0; o >>= 1) s += __shfl_xor_sync(0xffffffffu, s, o);
    if (lane == 0) sh[wid] = s;
    __syncthreads();
    if (tid == 0) {
        float t = 0.0f;
#pragma unroll
        for (int i = 0; i < 8; i++) t += sh[i];
        sh[0] = t;
    }
    __syncthreads();
    const float inv = 1.0f / sh[0];
#pragma unroll
    for (int i = 0; i < 8; i++) row[tid + 256 * i] = roundtf(v[i] * inv);
}

// ---------------------------------------------------------------------------
// Launch
// ---------------------------------------------------------------------------
extern "C" void kernel_launch(void* const* d_in, const int* in_sizes, int n_in,
                              void* d_out, int out_size)
{
    const float* x  = (const float*)d_in[0];
    const float* Wq = (const float*)d_in[1];
    const float* bq = (const float*)d_in[2];
    const float* Wk = (const float*)d_in[3];
    const float* bk = (const float*)d_in[4];
    const float* Wv = (const float*)d_in[5];
    const float* bv = (const float*)d_in[6];
    float* out = (float*)d_out;

    float *Xr, *Q, *K, *Vt, *Sc, *Wt, *bc;
    cudaGetSymbolAddress((void**)&Xr, g_Xr);
    cudaGetSymbolAddress((void**)&Q,  g_Q);
    cudaGetSymbolAddress((void**)&K,  g_K);
    cudaGetSymbolAddress((void**)&Vt, g_Vt);
    cudaGetSymbolAddress((void**)&Sc, g_S);
    cudaGetSymbolAddress((void**)&Wt, g_Wt);
    cudaGetSymbolAddress((void**)&bc, g_bc);

    cudaFuncSetAttribute(gemm_ca<true >, cudaFuncAttributeMaxDynamicSharedMemorySize, SMEM_SZ);
    cudaFuncSetAttribute(gemm_ca<false>, cudaFuncAttributeMaxDynamicSharedMemorySize, SMEM_SZ);

    // 0) Pre-round x; transpose+round weights (concat [1536][1024]); concat bias
    round_x<<<(MTOT * DIN / 4 + 255) / 256, 256>>>(x, Xr, MTOT * DIN / 4);
    const dim3 tb(32, 8), tg(DQK / 32, DIN / 32);
    transpose_k<<<tg, tb>>>(Wq, Wt,                       DIN, DQK);
    transpose_k<<<tg, tb>>>(Wk, Wt + (size_t)DQK * DIN,   DIN, DQK);
    transpose_k<<<tg, tb>>>(Wv, Wt + 2 * (size_t)DQK * DIN, DIN, DQK);
    concat_bias<<<6, 256>>>(bq, bk, bv, bc);

    const dim3 blk(256);

    // 1) Fused QKV projection: M=8192, N=1536, K=1024
    gemm_ca<true><<<dim3(NPROJ / BN, MTOT / BM, 1), blk, SMEM_SZ>>>(
        Xr, Wt, bc, 1.0f, Q, K, Vt, DIN, DIN, 0, DIN, 0, 0, 0);

    // 2) Scores: S = (Q @ K^T) / sqrt(512)  per batch 2048x2048x512
    const float scale = 0.044194173824159216f;
    gemm_ca<false><<<dim3(S_ / BN, S_ / BM, B_), blk, SMEM_SZ>>>(
        Q, K, nullptr, scale, Sc, nullptr, nullptr, DQK, DQK, S_, DQK,
        (long)S_ * DQK, (long)S_ * DQK, (long)S_ * S_);

    // 3) Softmax (stores tf32-rounded P)
    softmax2048<<<B_ * S_, blk>>>(Sc);

    // 4) Out = P @ Vt^T  per batch 2048x512x2048
    gemm_ca<false><<<dim3(DV / BN, S_ / BM, B_), blk, SMEM_SZ>>>(
        Sc, Vt, nullptr, 1.0f, out, nullptr, nullptr, S_, S_, DV, S_,
        (long)S_ * S_, (long)DV * S_, (long)S_ * DV);
}

// round 5
// speedup vs baseline: 4.8441x; 1.6745x over previous
#include <cuda_runtime.h>
#include <cuda_fp16.h>
#include <cstdint>

// ---------------------------------------------------------------------------
// SelfAttention, fp16 mma.sync (m16n8k16, fp32 accum) + ldmatrix + cp.async
// 3-stage pipeline. fp16 has the SAME 10-bit mantissa as tf32, so operand
// rounding error is unchanged; scores are kept fp32 (exp() would amplify
// fp16 storage error). B=4, S=2048, DIN=1024, DQK=DV=512, fp32 I/O.
// ---------------------------------------------------------------------------

constexpr int B_   = 4;
constexpr int S_   = 2048;
constexpr int DIN  = 1024;
constexpr int DQK  = 512;
constexpr int DV   = 512;
constexpr int MTOT = B_ * S_;    // 8192
constexpr int NPROJ = 3 * DQK;   // 1536

// Scratch (__device__ globals; allocation-free rule)
__device__ __half g_Xh [MTOT * DIN];
__device__ __half g_Wth[NPROJ * DIN];          // W^T concat [1536][1024]
__device__ __half g_Qh [MTOT * DQK];
__device__ __half g_Kh [MTOT * DQK];
__device__ __half g_Vth[MTOT * DV];            // per batch [DV][S]
__device__ __half g_Ph [(size_t)B_ * S_ * S_]; // probabilities
__device__ float  g_S  [(size_t)B_ * S_ * S_]; // raw scores (fp32!)
__device__ float  g_bc [NPROJ];

__device__ __forceinline__ uint32_t smem_u32(const void* p) {
    uint32_t a;
    asm("{ .reg .u64 t; cvta.to.shared.u64 t, %1; cvt.u32.u64 %0, t; }" : "=r"(a) : "l"(p));
    return a;
}
__device__ __forceinline__ uint32_t swz128(uint32_t off) {
    return off ^ ((off >> 3) & 0x70);
}

#define LDSM_X4(r0, r1, r2, r3, a)                                          \
    asm volatile("ldmatrix.sync.aligned.m8n8.x4.shared.b16 {%0,%1,%2,%3}, [%4];" \
                 : "=r"(r0), "=r"(r1), "=r"(r2), "=r"(r3) : "r"(a))

__device__ __forceinline__ void mma_f16(float c[4], const uint32_t a[4],
                                        uint32_t b0, uint32_t b1) {
    asm volatile(
        "mma.sync.aligned.m16n8k16.row.col.f32.f16.f16.f32 "
        "{%0,%1,%2,%3}, {%4,%5,%6,%7}, {%8,%9}, {%0,%1,%2,%3};"
        : "+f"(c[0]), "+f"(c[1]), "+f"(c[2]), "+f"(c[3])
        : "r"(a[0]), "r"(a[1]), "r"(a[2]), "r"(a[3]), "r"(b0), "r"(b1));
}

__device__ __forceinline__ void cp16(uint32_t s, const void* g) {
    asm volatile("cp.async.cg.shared.global [%0], [%1], 16;" :: "r"(s), "l"(g));
}
#define CP_COMMIT() asm volatile("cp.async.commit_group;" ::: "memory")
#define CP_WAIT1()  asm volatile("cp.async.wait_group 1;"  ::: "memory")

// ---------------------------------------------------------------------------
// GEMM: C = scale * (A[M,K] @ B[N,K]^T) (+ bias); fp16 operands, fp32 accum.
// CTA 128x128, K-chunk 64 halves (128B/row, one SW128 atom), 256 threads,
// 8 warps of 32(m)x64(n), 3-stage cp.async pipeline (96 KB smem, 2 CTA/SM).
// PROJ=true: fused QKV projection epilogue: +bias, fp16 stores,
//   cols [0,512)->Qh, [512,1024)->Kh, [1024,1536)->Vth (transposed/batch).
// PROJ=false: fp32 store of scale*acc (QK scores / PV output).
// ---------------------------------------------------------------------------
constexpr int BM = 128, BN = 128, BKC = 64, STAGES = 3;
constexpr int TILE_B  = 128 * 128;            // 16 KB (128 rows x 128 B)
constexpr int STAGE_B = 2 * TILE_B;           // 32 KB
constexpr int SMEM_SZ = STAGES * STAGE_B;     // 96 KB

__device__ __forceinline__ void copy_tile(uint32_t sdst, const __half* __restrict__ src,
                                          int ld, int k0, int tid) {
    const int q = tid & 7, r0 = tid >> 3;
#pragma unroll
    for (int p = 0; p < 4; p++) {
        const int row = r0 + p * 32;
        cp16(sdst + swz128((uint32_t)(row * 128 + q * 16)),
             src + (size_t)row * ld + k0 + q * 8);
    }
}

template <bool PROJ>
__global__ __launch_bounds__(256, 2)
void gemm_h(const __half* __restrict__ A, const __half* __restrict__ Bm,
            const float* __restrict__ bias, float scale,
            float* __restrict__ Cf, __half* __restrict__ C0,
            __half* __restrict__ C1, __half* __restrict__ C2,
            int lda, int ldb, int ldc, int K,
            long sA, long sB, long sC)
{
    extern __shared__ __align__(1024) char smem[];
    const uint32_t sb = smem_u32(smem);

    A  += (long)blockIdx.z * sA;
    Bm += (long)blockIdx.z * sB;
    float* C = Cf + (long)blockIdx.z * sC;

    const int m0   = blockIdx.y * BM;
    const int n0   = blockIdx.x * BN;
    const int tid  = threadIdx.x;
    const int lane = tid & 31;
    const int wid  = tid >> 5;
    const int wm   = wid & 3;
    const int wn   = wid >> 2;

    const int lr  = lane & 7;
    const int b8  = lane >> 3;
    const int aro = (b8 & 1) * 8 + lr;   // A: m offset within m16
    const int ach = b8 >> 1;             // A: k half-tile (0 / +8 halves)
    const int bro = (b8 >> 1) * 8 + lr;  // B: n offset within n16
    const int bch = b8 & 1;              // B: k half-tile

    const __half* Ab = A  + (size_t)m0 * lda;
    const __half* Bb = Bm + (size_t)n0 * ldb;
    const int NC = K / BKC;

    float acc[2][8][4];
#pragma unroll
    for (int i = 0; i < 2; i++)
#pragma unroll
        for (int j = 0; j < 8; j++)
#pragma unroll
            for (int r = 0; r < 4; r++) acc[i][j][r] = 0.0f;

    // prologue: stages 0,1 in flight
    copy_tile(sb,                    Ab, lda, 0, tid);
    copy_tile(sb + TILE_B,           Bb, ldb, 0, tid);
    CP_COMMIT();
    copy_tile(sb + STAGE_B,          Ab, lda, BKC, tid);
    copy_tile(sb + STAGE_B + TILE_B, Bb, ldb, BKC, tid);
    CP_COMMIT();

    int bufc = 0, bufn = 2;
    for (int c = 0; c < NC; c++) {
        CP_WAIT1();
        __syncthreads();

        if (c + 2 < NC) {
            const uint32_t d = sb + bufn * STAGE_B;
            copy_tile(d,          Ab, lda, (c + 2) * BKC, tid);
            copy_tile(d + TILE_B, Bb, ldb, (c + 2) * BKC, tid);
        }
        CP_COMMIT();

        const uint32_t baseA = sb + bufc * STAGE_B;
        const uint32_t baseB = baseA + TILE_B;
#pragma unroll
        for (int ks = 0; ks < 4; ks++) {        // 4 x k16 = 64 halves
            uint32_t a[2][4];
#pragma unroll
            for (int mi = 0; mi < 2; mi++) {
                const uint32_t off =
                    (uint32_t)((wm * 32 + mi * 16 + aro) * 128 + ks * 32 + ach * 16);
                LDSM_X4(a[mi][0], a[mi][1], a[mi][2], a[mi][3], baseA + swz128(off));
            }
            uint32_t bq[4][4];
#pragma unroll
            for (int p = 0; p < 4; p++) {
                const uint32_t off =
                    (uint32_t)((wn * 64 + p * 16 + bro) * 128 + ks * 32 + bch * 16);
                LDSM_X4(bq[p][0], bq[p][1], bq[p][2], bq[p][3], baseB + swz128(off));
            }
#pragma unroll
            for (int mi = 0; mi < 2; mi++)
#pragma unroll
                for (int ni = 0; ni < 8; ni++)
                    mma_f16(acc[mi][ni], a[mi],
                            bq[ni >> 1][(ni & 1) * 2], bq[ni >> 1][(ni & 1) * 2 + 1]);
        }
        bufc = (bufc == 2) ? 0 : bufc + 1;
        bufn = (bufn == 2) ? 0 : bufn + 1;
    }

    // epilogue
#pragma unroll
    for (int mi = 0; mi < 2; mi++) {
#pragma unroll
        for (int ni = 0; ni < 8; ni++) {
            const int row = m0 + wm * 32 + mi * 16 + (lane >> 2);
            const int col = n0 + wn * 64 + ni * 8 + 2 * (lane & 3);
            if (PROJ) {
                const float b0 = __ldg(bias + col);
                const float b1 = __ldg(bias + col + 1);
                const __half v00 = __float2half_rn(acc[mi][ni][0] + b0);
                const __half v01 = __float2half_rn(acc[mi][ni][1] + b1);
                const __half v10 = __float2half_rn(acc[mi][ni][2] + b0);
                const __half v11 = __float2half_rn(acc[mi][ni][3] + b1);
                if (col < 1024) {
                    __half* dst = (col < 512) ? C0 : C1;
                    const int cc = col & 511;
                    *reinterpret_cast<__half2*>(dst + (size_t)row * DQK + cc) =
                        __halves2half2(v00, v01);
                    *reinterpret_cast<__half2*>(dst + (size_t)(row + 8) * DQK + cc) =
                        __halves2half2(v10, v11);
                } else {
                    const int vc = col - 1024;
                    const int bb0 = row >> 11, s0 = row & 2047;
                    const int bb1 = (row + 8) >> 11, s1 = (row + 8) & 2047;
                    C2[((size_t)(bb0 * DV + vc))     * S_ + s0] = v00;
                    C2[((size_t)(bb0 * DV + vc + 1)) * S_ + s0] = v01;
                    C2[((size_t)(bb1 * DV + vc))     * S_ + s1] = v10;
                    C2[((size_t)(bb1 * DV + vc + 1)) * S_ + s1] = v11;
                }
            } else {
                float* c0 = C + (size_t)row * ldc + col;
                c0[0] = acc[mi][ni][0] * scale;
                c0[1] = acc[mi][ni][1] * scale;
                float* c1 = C + (size_t)(row + 8) * ldc + col;
                c1[0] = acc[mi][ni][2] * scale;
                c1[1] = acc[mi][ni][3] * scale;
            }
        }
    }
}

// ---------------------------------------------------------------------------
// x -> fp16 copy (4 elems/thread)
// ---------------------------------------------------------------------------
__global__ __launch_bounds__(256)
void cvt_x(const float* __restrict__ in, __half* __restrict__ out, int n4)
{
    const int i = blockIdx.x * blockDim.x + threadIdx.x;
    if (i < n4) {
        float4 v = reinterpret_cast<const float4*>(in)[i];
        __half2 h0 = __floats2half2_rn(v.x, v.y);
        __half2 h1 = __floats2half2_rn(v.z, v.w);
        reinterpret_cast<__half2*>(out)[2 * i]     = h0;
        reinterpret_cast<__half2*>(out)[2 * i + 1] = h1;
    }
}

// ---------------------------------------------------------------------------
// Weight transpose + fp16 convert: out[C][R] = half(in[R][C])
// ---------------------------------------------------------------------------
__global__ __launch_bounds__(256)
void transpose_h(const float* __restrict__ in, __half* __restrict__ out, int R, int C)
{
    __shared__ float t[32][33];
    const int bx = blockIdx.x * 32, by = blockIdx.y * 32;
    const int tx = threadIdx.x, ty = threadIdx.y;
#pragma unroll
    for (int i = 0; i < 4; i++)
        t[ty + 8 * i][tx] = in[(size_t)(by + ty + 8 * i) * C + bx + tx];
    __syncthreads();
#pragma unroll
    for (int i = 0; i < 4; i++)
        out[(size_t)(bx + ty + 8 * i) * R + by + tx] = __float2half_rn(t[tx][ty + 8 * i]);
}

__global__ void concat_bias(const float* __restrict__ bq, const float* __restrict__ bk,
                            const float* __restrict__ bv, float* __restrict__ bc)
{
    const int i = blockIdx.x * blockDim.x + threadIdx.x;
    if (i < DQK)            bc[i] = bq[i];
    else if (i < 2 * DQK)   bc[i] = bk[i - DQK];
    else if (i < 3 * DQK)   bc[i] = bv[i - 2 * DQK];
}

// ---------------------------------------------------------------------------
// Row softmax over 2048 cols: reads fp32 scores, writes fp16 probabilities.
// Contiguous 8-per-thread layout: float4 loads, half2 stores, fully coalesced.
// ---------------------------------------------------------------------------
__global__ __launch_bounds__(256)
void softmax2048(const float* __restrict__ Sm, __half* __restrict__ Pm)
{
    const int tid = threadIdx.x;
    const float* row  = Sm + (size_t)blockIdx.x * 2048;
    __half*      rowp = Pm + (size_t)blockIdx.x * 2048;

    float4 u0 = reinterpret_cast<const float4*>(row)[2 * tid];
    float4 u1 = reinterpret_cast<const float4*>(row)[2 * tid + 1];
    float v[8] = {u0.x, u0.y, u0.z, u0.w, u1.x, u1.y, u1.z, u1.w};

    float mx = -3.4e38f;
#pragma unroll
    for (int i = 0; i < 8; i++) mx = fmaxf(mx, v[i]);

    __shared__ float sh[8];
    const int wid = tid >> 5, lane = tid & 31;
#pragma unroll
    for (int o = 16; o > 0; o >>= 1) mx = fmaxf(mx, __shfl_xor_sync(0xffffffffu, mx, o));
    if (lane == 0) sh[wid] = mx;
    __syncthreads();
    if (tid == 0) {
        float m2 = sh[0];
#pragma unroll
        for (int i = 1; i < 8; i++) m2 = fmaxf(m2, sh[i]);
        sh[0] = m2;
    }
    __syncthreads();
    mx = sh[0];
    __syncthreads();

    float s = 0.0f;
#pragma unroll
    for (int i = 0; i < 8; i++) { v[i] = __expf(v[i] - mx); s += v[i]; }
#pragma unroll
    for (int o = 16; o > 0; o >>= 1) s += __shfl_xor_sync(0xffffffffu, s, o);
    if (lane == 0) sh[wid] = s;
    __syncthreads();
    if (tid == 0) {
        float t = 0.0f;
#pragma unroll
        for (int i = 0; i < 8; i++) t += sh[i];
        sh[0] = t;
    }
    __syncthreads();
    const float inv = 1.0f / sh[0];

#pragma unroll
    for (int i = 0; i < 4; i++)
        reinterpret_cast<__half2*>(rowp)[4 * tid + i] =
            __floats2half2_rn(v[2 * i] * inv, v[2 * i + 1] * inv);
}

// ---------------------------------------------------------------------------
// Launch
// ---------------------------------------------------------------------------
extern "C" void kernel_launch(void* const* d_in, const int* in_sizes, int n_in,
                              void* d_out, int out_size)
{
    const float* x  = (const float*)d_in[0];
    const float* Wq = (const float*)d_in[1];
    const float* bq = (const float*)d_in[2];
    const float* Wk = (const float*)d_in[3];
    const float* bk = (const float*)d_in[4];
    const float* Wv = (const float*)d_in[5];
    const float* bv = (const float*)d_in[6];
    float* out = (float*)d_out;

    __half *Xh, *Wth, *Qh, *Kh, *Vth, *Ph;
    float *Sc, *bc;
    cudaGetSymbolAddress((void**)&Xh,  g_Xh);
    cudaGetSymbolAddress((void**)&Wth, g_Wth);
    cudaGetSymbolAddress((void**)&Qh,  g_Qh);
    cudaGetSymbolAddress((void**)&Kh,  g_Kh);
    cudaGetSymbolAddress((void**)&Vth, g_Vth);
    cudaGetSymbolAddress((void**)&Ph,  g_Ph);
    cudaGetSymbolAddress((void**)&Sc,  g_S);
    cudaGetSymbolAddress((void**)&bc,  g_bc);

    cudaFuncSetAttribute(gemm_h<true >, cudaFuncAttributeMaxDynamicSharedMemorySize, SMEM_SZ);
    cudaFuncSetAttribute(gemm_h<false>, cudaFuncAttributeMaxDynamicSharedMemorySize, SMEM_SZ);

    // 0) Convert x; transpose+convert weights; concat bias
    cvt_x<<<(MTOT * DIN / 4 + 255) / 256, 256>>>(x, Xh, MTOT * DIN / 4);
    const dim3 tb(32, 8), tg(DQK / 32, DIN / 32);
    transpose_h<<<tg, tb>>>(Wq, Wth,                         DIN, DQK);
    transpose_h<<<tg, tb>>>(Wk, Wth + (size_t)DQK * DIN,     DIN, DQK);
    transpose_h<<<tg, tb>>>(Wv, Wth + 2 * (size_t)DQK * DIN, DIN, DQK);
    concat_bias<<<6, 256>>>(bq, bk, bv, bc);

    const dim3 blk(256);

    // 1) Fused QKV projection: M=8192, N=1536, K=1024
    gemm_h<true><<<dim3(NPROJ / BN, MTOT / BM, 1), blk, SMEM_SZ>>>(
        Xh, Wth, bc, 1.0f, nullptr, Qh, Kh, Vth, DIN, DIN, 0, DIN, 0, 0, 0);

    // 2) Scores (fp32): S = (Q @ K^T) / sqrt(512)  per batch 2048x2048x512
    const float scale = 0.044194173824159216f;
    gemm_h<false><<<dim3(S_ / BN, S_ / BM, B_), blk, SMEM_SZ>>>(
        Qh, Kh, nullptr, scale, Sc, nullptr, nullptr, nullptr, DQK, DQK, S_, DQK,
        (long)S_ * DQK, (long)S_ * DQK, (long)S_ * S_);

    // 3) Softmax: fp32 scores -> fp16 probabilities
    softmax2048<<<B_ * S_, blk>>>(Sc, Ph);

    // 4) Out (fp32) = P @ Vt^T  per batch 2048x512x2048
    gemm_h<false><<<dim3(DV / BN, S_ / BM, B_), blk, SMEM_SZ>>>(
        Ph, Vth, nullptr, 1.0f, out, nullptr, nullptr, nullptr, S_, S_, DV, S_,
        (long)S_ * S_, (long)DV * S_, (long)S_ * DV);
}